// round 9
// baseline (speedup 1.0000x reference)
#include <cuda_runtime.h>
#include <cuda_bf16.h>
#include <cstdint>
#include <math.h>

#define SEQ 2048
#define DM 2048
#define H 16
#define E 128
#define NE3 384

// ----------------- scratch (static device allocations) -----------------
__device__ __nv_bfloat16 g_xh[(size_t)SEQ * DM];
__device__ __nv_bfloat16 g_xl[(size_t)SEQ * DM];
__device__ __nv_bfloat16 g_wth[(size_t)H * NE3 * DM];    // w transposed: [h][n][k]
__device__ __nv_bfloat16 g_wtl[(size_t)H * NE3 * DM];
__device__ __nv_bfloat16 g_qkh[(size_t)H * SEQ * 256];   // [h][s][Q(0:128)|K(128:256)] hi
__device__ __nv_bfloat16 g_qkl[(size_t)H * SEQ * 256];   // lo
__device__ __nv_bfloat16 g_vth[(size_t)H * E * SEQ];     // V^T: [h][e][t] hi
__device__ __nv_bfloat16 g_vtl[(size_t)H * E * SEQ];     // lo

__device__ __forceinline__ uint32_t smem_u32(const void* p) {
    uint32_t a;
    asm("{ .reg .u64 t; cvta.to.shared.u64 t, %1; cvt.u32.u64 %0, t; }" : "=r"(a) : "l"(p));
    return a;
}
__device__ __forceinline__ float fexp2(float x) {
    float r;
    asm("ex2.approx.f32 %0, %1;" : "=f"(r) : "f"(x));
    return r;
}

#define LDSM4(r, a)                                                              \
    asm volatile("ldmatrix.sync.aligned.m8n8.x4.shared.b16 {%0,%1,%2,%3}, [%4];" \
                 : "=r"((r)[0]), "=r"((r)[1]), "=r"((r)[2]), "=r"((r)[3]) : "r"(a))
#define MMA_BF16(d, a, b0, b1)                                                       \
    asm volatile("mma.sync.aligned.m16n8k16.row.col.f32.bf16.bf16.f32 "              \
                 "{%0,%1,%2,%3},{%4,%5,%6,%7},{%8,%9},{%0,%1,%2,%3};"                \
                 : "+f"((d)[0]), "+f"((d)[1]), "+f"((d)[2]), "+f"((d)[3])            \
                 : "r"((a)[0]), "r"((a)[1]), "r"((a)[2]), "r"((a)[3]), "r"(b0), "r"(b1))

__device__ __forceinline__ uint32_t pack_split(float a, float b, uint32_t& lo) {
    __nv_bfloat16 ha = __float2bfloat16(a), hb = __float2bfloat16(b);
    __nv_bfloat16 la = __float2bfloat16(a - __bfloat162float(ha));
    __nv_bfloat16 lb = __float2bfloat16(b - __bfloat162float(hb));
    lo = (uint32_t)__bfloat16_as_ushort(la) | ((uint32_t)__bfloat16_as_ushort(lb) << 16);
    return (uint32_t)__bfloat16_as_ushort(ha) | ((uint32_t)__bfloat16_as_ushort(hb) << 16);
}

// ================= GEMM: C(bf16 hi/lo) = A * B^T, bf16x3 =================
// A:[M][K] K-major (lda), B:[N][K] K-major (ldb). Cols < thr scaled by alpha0.
// Tiles 128x32 bf16 = 8KB, conflict-free via additive chunk swizzle (no padding).
constexpr int BM = 128, BN = 128, BK = 32;
constexpr int TILE_BYTES  = 128 * 64;           // 8192 B
constexpr int STAGE_BYTES = 4 * TILE_BYTES;     // Ah, Al, Bh, Bl = 32768 B
constexpr int NSTAGE = 3;                       // 98304 B total -> 2 CTAs/SM

__device__ __forceinline__ uint32_t gswz(int row, int c) {
    return (uint32_t)(row * 64 + (((c + (row >> 1)) & 3) << 4));
}

__device__ __forceinline__ void ld_tile(uint32_t dst, const __nv_bfloat16* src, int ld, int tid) {
    #pragma unroll
    for (int j = 0; j < 2; j++) {
        int idx = tid + j * 256;        // 512 chunks: 128 rows x 4 x 16B
        int row = idx >> 2, c = idx & 3;
        uint32_t s = dst + gswz(row, c);
        const __nv_bfloat16* g = src + (size_t)row * ld + c * 8;
        asm volatile("cp.async.cg.shared.global [%0], [%1], 16;" :: "r"(s), "l"(g));
    }
}

__global__ void __launch_bounds__(256, 2)
gemm_bf16x3(const __nv_bfloat16* __restrict__ Ah, const __nv_bfloat16* __restrict__ Al,
            const __nv_bfloat16* __restrict__ Bh, const __nv_bfloat16* __restrict__ Bl,
            __nv_bfloat16* __restrict__ Ch, __nv_bfloat16* __restrict__ Cl,
            int K, int lda, int ldb, int ldc,
            long long aB, long long bB, long long cB, float alpha0, int thr)
{
    extern __shared__ __align__(1024) char dsm[];
    const uint32_t base = smem_u32(dsm);

    const int tid = threadIdx.x;
    const int lane = tid & 31, wid = tid >> 5;
    const int wm = wid & 1;
    const int wn = wid >> 1;
    const int m0 = blockIdx.x * BM, n0 = blockIdx.y * BN;
    const long long z = blockIdx.z;

    const __nv_bfloat16* pAh = Ah + z * aB + (size_t)m0 * lda;
    const __nv_bfloat16* pAl = Al + z * aB + (size_t)m0 * lda;
    const __nv_bfloat16* pBh = Bh + z * bB + (size_t)n0 * ldb;
    const __nv_bfloat16* pBl = Bl + z * bB + (size_t)n0 * ldb;

    const int a_row0 = wm * 64 + (lane & 15);
    const int a_csel = lane >> 4;
    const int b_row0 = wn * 32 + ((lane >> 4) << 3) + (lane & 7);
    const int b_csel = (lane >> 3) & 1;

    float acc[4][4][4] = {};

    const int nIter = K >> 5;
    #pragma unroll
    for (int s = 0; s < NSTAGE - 1; s++) {
        uint32_t sb = base + s * STAGE_BYTES;
        ld_tile(sb,                  pAh + s * BK, lda, tid);
        ld_tile(sb + TILE_BYTES,     pAl + s * BK, lda, tid);
        ld_tile(sb + 2 * TILE_BYTES, pBh + s * BK, ldb, tid);
        ld_tile(sb + 3 * TILE_BYTES, pBl + s * BK, ldb, tid);
        asm volatile("cp.async.commit_group;" ::: "memory");
    }

    for (int i = 0; i < nIter; i++) {
        asm volatile("cp.async.wait_group %0;" :: "n"(NSTAGE - 2) : "memory");
        __syncthreads();

        const int c = i + NSTAGE - 1;
        if (c < nIter) {
            uint32_t sb = base + (c % NSTAGE) * STAGE_BYTES;
            ld_tile(sb,                  pAh + c * BK, lda, tid);
            ld_tile(sb + TILE_BYTES,     pAl + c * BK, lda, tid);
            ld_tile(sb + 2 * TILE_BYTES, pBh + c * BK, ldb, tid);
            ld_tile(sb + 3 * TILE_BYTES, pBl + c * BK, ldb, tid);
        }
        asm volatile("cp.async.commit_group;" ::: "memory");   // uniform accounting

        const uint32_t sb   = base + (i % NSTAGE) * STAGE_BYTES;
        const uint32_t sA_h = sb;
        const uint32_t sA_l = sb + TILE_BYTES;
        const uint32_t sB_h = sb + 2 * TILE_BYTES;
        const uint32_t sB_l = sb + 3 * TILE_BYTES;

        #pragma unroll
        for (int kk = 0; kk < 2; kk++) {
            uint32_t fah[4][4], fal[4][4];
            #pragma unroll
            for (int mt = 0; mt < 4; mt++) {
                const uint32_t o = gswz(a_row0 + mt * 16, kk * 2 + a_csel);
                LDSM4(fah[mt], sA_h + o);
                LDSM4(fal[mt], sA_l + o);
            }
            #pragma unroll
            for (int nr = 0; nr < 2; nr++) {
                const uint32_t o = gswz(b_row0 + nr * 16, kk * 2 + b_csel);
                uint32_t fbh[4], fbl[4];
                LDSM4(fbh, sB_h + o);
                LDSM4(fbl, sB_l + o);
                // term-major: consecutive MMAs hit different accumulators
                // (per-acc order hh->hl->lh preserved => bit-identical numerics)
                #pragma unroll
                for (int mt = 0; mt < 4; mt++) {
                    MMA_BF16(acc[mt][nr * 2],     fah[mt], fbh[0], fbh[1]);
                    MMA_BF16(acc[mt][nr * 2 + 1], fah[mt], fbh[2], fbh[3]);
                }
                #pragma unroll
                for (int mt = 0; mt < 4; mt++) {
                    MMA_BF16(acc[mt][nr * 2],     fah[mt], fbl[0], fbl[1]);
                    MMA_BF16(acc[mt][nr * 2 + 1], fah[mt], fbl[2], fbl[3]);
                }
                #pragma unroll
                for (int mt = 0; mt < 4; mt++) {
                    MMA_BF16(acc[mt][nr * 2],     fal[mt], fbh[0], fbh[1]);
                    MMA_BF16(acc[mt][nr * 2 + 1], fal[mt], fbh[2], fbh[3]);
                }
            }
        }
    }

    // epilogue: scale (cols < thr) and write bf16 hi/lo pairs
    __nv_bfloat16* ch = Ch + z * cB;
    __nv_bfloat16* cl = Cl + z * cB;
    const int er = m0 + wm * 64 + (lane >> 2);
    const int ecb = n0 + wn * 32 + (lane & 3) * 2;
    #pragma unroll
    for (int mt = 0; mt < 4; mt++) {
        #pragma unroll
        for (int nt = 0; nt < 4; nt++) {
            const int col = ecb + nt * 8;
            const float a = (col < thr) ? alpha0 : 1.0f;
            const size_t o0 = (size_t)(er + mt * 16) * ldc + col;
            const size_t o1 = o0 + 8 * (size_t)ldc;
            uint32_t lo, hi;
            hi = pack_split(acc[mt][nt][0] * a, acc[mt][nt][1] * a, lo);
            *reinterpret_cast<uint32_t*>(ch + o0) = hi;
            *reinterpret_cast<uint32_t*>(cl + o0) = lo;
            hi = pack_split(acc[mt][nt][2] * a, acc[mt][nt][3] * a, lo);
            *reinterpret_cast<uint32_t*>(ch + o1) = hi;
            *reinterpret_cast<uint32_t*>(cl + o1) = lo;
        }
    }
}

// ================= fused flash attention =================
constexpr int FT = 32768;                 // bytes per tile
#define FSWZ(row, c) ((uint32_t)((row) * 256 + (((c) ^ ((row) & 7)) << 4)))

__global__ void __launch_bounds__(256, 1)
flash_attn(const __nv_bfloat16* __restrict__ qk_h, const __nv_bfloat16* __restrict__ qk_l,
           const __nv_bfloat16* __restrict__ vt_h, const __nv_bfloat16* __restrict__ vt_l,
           float* __restrict__ out)
{
    extern __shared__ __align__(1024) char fsm[];
    const uint32_t sQh = smem_u32(fsm);
    const uint32_t sQl = sQh + FT, sKh = sQh + 2 * FT, sKl = sQh + 3 * FT;
    const uint32_t sVh = sQh + 4 * FT, sVl = sQh + 5 * FT;

    const int tid = threadIdx.x, lane = tid & 31, wr = tid >> 5;
    const int q0 = blockIdx.x * 128;
    const int h = blockIdx.y;
    const size_t qkB = (size_t)h * SEQ * 256;
    const size_t vB  = (size_t)h * E * SEQ;

    #define FLD(dst, src, ld)                                                             \
        do {                                                                              \
            _Pragma("unroll")                                                             \
            for (int j_ = 0; j_ < 8; j_++) {                                              \
                int idx_ = tid + j_ * 256;                                                \
                int row_ = idx_ >> 4, c_ = idx_ & 15;                                     \
                uint32_t d_ = (dst) + FSWZ(row_, c_);                                     \
                const __nv_bfloat16* g_ = (src) + (size_t)row_ * (ld) + c_ * 8;           \
                asm volatile("cp.async.cg.shared.global [%0], [%1], 16;" :: "r"(d_), "l"(g_)); \
            }                                                                             \
        } while (0)

    // warmup: Q + K0
    FLD(sQh, qk_h + qkB + (size_t)q0 * 256, 256);
    FLD(sQl, qk_l + qkB + (size_t)q0 * 256, 256);
    FLD(sKh, qk_h + qkB + 128, 256);
    FLD(sKl, qk_l + qkB + 128, 256);
    asm volatile("cp.async.commit_group;" ::: "memory");

    float o[16][4] = {};
    float m01 = -1e30f, m23 = -1e30f, l01 = 0.f, l23 = 0.f;
    const float LOG2E = 1.4426950408889634f;

    const int qrow = wr * 16 + (lane & 15);
    const int nrow = ((lane >> 4) << 3) + (lane & 7);

    for (int j = 0; j < 16; j++) {
        asm volatile("cp.async.wait_group 0;" ::: "memory");
        __syncthreads();    // K_j ready; all warps done with V_{j-1}

        // prefetch V_j
        FLD(sVh, vt_h + vB + j * 128, SEQ);
        FLD(sVl, vt_l + vB + j * 128, SEQ);
        asm volatile("cp.async.commit_group;" ::: "memory");

        // ---- S = Q * K_j^T  (bf16x3, np pairs, term-major) ----
        float s[16][4] = {};
        #pragma unroll
        for (int ks = 0; ks < 8; ks++) {
            const int cA = ks * 2 + (lane >> 4);
            const uint32_t aoff = FSWZ(qrow, cA);
            uint32_t qh_f[4], ql_f[4];
            LDSM4(qh_f, sQh + aoff);
            LDSM4(ql_f, sQl + aoff);
            const int cB = ks * 2 + ((lane >> 3) & 1);
            #pragma unroll
            for (int npp = 0; npp < 4; npp++) {
                uint32_t kh2[2][4], kl2[2][4];
                #pragma unroll
                for (int p = 0; p < 2; p++) {
                    const int br = (npp * 2 + p) * 16 + nrow;
                    const uint32_t boff = FSWZ(br, cB);
                    LDSM4(kh2[p], sKh + boff);
                    LDSM4(kl2[p], sKl + boff);
                }
                #pragma unroll
                for (int p = 0; p < 2; p++) {
                    MMA_BF16(s[npp * 4 + 2 * p],     qh_f, kh2[p][0], kh2[p][1]);
                    MMA_BF16(s[npp * 4 + 2 * p + 1], qh_f, kh2[p][2], kh2[p][3]);
                }
                #pragma unroll
                for (int p = 0; p < 2; p++) {
                    MMA_BF16(s[npp * 4 + 2 * p],     qh_f, kl2[p][0], kl2[p][1]);
                    MMA_BF16(s[npp * 4 + 2 * p + 1], qh_f, kl2[p][2], kl2[p][3]);
                }
                #pragma unroll
                for (int p = 0; p < 2; p++) {
                    MMA_BF16(s[npp * 4 + 2 * p],     ql_f, kh2[p][0], kh2[p][1]);
                    MMA_BF16(s[npp * 4 + 2 * p + 1], ql_f, kh2[p][2], kh2[p][3]);
                }
            }
        }

        asm volatile("cp.async.wait_group 0;" ::: "memory");
        __syncthreads();    // V_j ready; all warps done reading K_j

        // prefetch K_{j+1}
        if (j + 1 < 16) {
            FLD(sKh, qk_h + qkB + (size_t)(j + 1) * 128 * 256 + 128, 256);
            FLD(sKl, qk_l + qkB + (size_t)(j + 1) * 128 * 256 + 128, 256);
        }
        asm volatile("cp.async.commit_group;" ::: "memory");

        // ---- online softmax ----
        float nm0 = m01, nm1 = m23;
        #pragma unroll
        for (int nt = 0; nt < 16; nt++) {
            nm0 = fmaxf(nm0, fmaxf(s[nt][0], s[nt][1]));
            nm1 = fmaxf(nm1, fmaxf(s[nt][2], s[nt][3]));
        }
        nm0 = fmaxf(nm0, __shfl_xor_sync(0xffffffffu, nm0, 1));
        nm0 = fmaxf(nm0, __shfl_xor_sync(0xffffffffu, nm0, 2));
        nm1 = fmaxf(nm1, __shfl_xor_sync(0xffffffffu, nm1, 1));
        nm1 = fmaxf(nm1, __shfl_xor_sync(0xffffffffu, nm1, 2));
        const float sc0 = fexp2((m01 - nm0) * LOG2E);
        const float sc1 = fexp2((m23 - nm1) * LOG2E);
        m01 = nm0; m23 = nm1;
        float rs0 = 0.f, rs1 = 0.f;
        #pragma unroll
        for (int nt = 0; nt < 16; nt++) {
            s[nt][0] = fexp2((s[nt][0] - m01) * LOG2E);
            s[nt][1] = fexp2((s[nt][1] - m01) * LOG2E);
            s[nt][2] = fexp2((s[nt][2] - m23) * LOG2E);
            s[nt][3] = fexp2((s[nt][3] - m23) * LOG2E);
            rs0 += s[nt][0] + s[nt][1];
            rs1 += s[nt][2] + s[nt][3];
        }
        rs0 += __shfl_xor_sync(0xffffffffu, rs0, 1);
        rs0 += __shfl_xor_sync(0xffffffffu, rs0, 2);
        rs1 += __shfl_xor_sync(0xffffffffu, rs1, 1);
        rs1 += __shfl_xor_sync(0xffffffffu, rs1, 2);
        l01 = l01 * sc0 + rs0;
        l23 = l23 * sc1 + rs1;
        #pragma unroll
        for (int nt = 0; nt < 16; nt++) {
            o[nt][0] *= sc0; o[nt][1] *= sc0;
            o[nt][2] *= sc1; o[nt][3] *= sc1;
        }

        // ---- O += P * V  (bf16x3, ep pairs, term-major) ----
        #pragma unroll
        for (int ks = 0; ks < 8; ks++) {
            uint32_t ah_f[4], al_f[4];
            ah_f[0] = pack_split(s[2 * ks][0],     s[2 * ks][1],     al_f[0]);
            ah_f[1] = pack_split(s[2 * ks][2],     s[2 * ks][3],     al_f[1]);
            ah_f[2] = pack_split(s[2 * ks + 1][0], s[2 * ks + 1][1], al_f[2]);
            ah_f[3] = pack_split(s[2 * ks + 1][2], s[2 * ks + 1][3], al_f[3]);
            const int cV = ks * 2 + ((lane >> 3) & 1);
            #pragma unroll
            for (int epp = 0; epp < 4; epp++) {
                uint32_t vh2[2][4], vl2[2][4];
                #pragma unroll
                for (int p = 0; p < 2; p++) {
                    const int vr = (epp * 2 + p) * 16 + nrow;
                    const uint32_t voff = FSWZ(vr, cV);
                    LDSM4(vh2[p], sVh + voff);
                    LDSM4(vl2[p], sVl + voff);
                }
                #pragma unroll
                for (int p = 0; p < 2; p++) {
                    MMA_BF16(o[epp * 4 + 2 * p],     ah_f, vh2[p][0], vh2[p][1]);
                    MMA_BF16(o[epp * 4 + 2 * p + 1], ah_f, vh2[p][2], vh2[p][3]);
                }
                #pragma unroll
                for (int p = 0; p < 2; p++) {
                    MMA_BF16(o[epp * 4 + 2 * p],     ah_f, vl2[p][0], vl2[p][1]);
                    MMA_BF16(o[epp * 4 + 2 * p + 1], ah_f, vl2[p][2], vl2[p][3]);
                }
                #pragma unroll
                for (int p = 0; p < 2; p++) {
                    MMA_BF16(o[epp * 4 + 2 * p],     al_f, vh2[p][0], vh2[p][1]);
                    MMA_BF16(o[epp * 4 + 2 * p + 1], al_f, vh2[p][2], vh2[p][3]);
                }
            }
        }
    }

    // epilogue
    const float inv0 = 1.0f / l01, inv1 = 1.0f / l23;
    const int row = q0 + wr * 16 + (lane >> 2);
    float* po = out + (size_t)row * DM + h * 128 + (lane & 3) * 2;
    #pragma unroll
    for (int nt = 0; nt < 16; nt++) {
        float2 v0 = { o[nt][0] * inv0, o[nt][1] * inv0 };
        float2 v1 = { o[nt][2] * inv1, o[nt][3] * inv1 };
        *reinterpret_cast<float2*>(po + nt * 8) = v0;
        *reinterpret_cast<float2*>(po + 8 * DM + nt * 8) = v1;
    }
}

// ----------------- fp32 -> bf16 hi/lo split (x) -----------------
__global__ void split_f32(const float* __restrict__ s,
                          __nv_bfloat16* __restrict__ hi, __nv_bfloat16* __restrict__ lo,
                          size_t nelem)
{
    size_t i = (size_t)blockIdx.x * blockDim.x + threadIdx.x;
    size_t stride = (size_t)gridDim.x * blockDim.x;
    for (size_t p = i * 4; p < nelem; p += stride * 4) {
        float4 v = *reinterpret_cast<const float4*>(s + p);
        uint32_t l0, l1;
        uint32_t h0 = pack_split(v.x, v.y, l0);
        uint32_t h1 = pack_split(v.z, v.w, l1);
        *reinterpret_cast<uint32_t*>(hi + p)     = h0;
        *reinterpret_cast<uint32_t*>(hi + p + 2) = h1;
        *reinterpret_cast<uint32_t*>(lo + p)     = l0;
        *reinterpret_cast<uint32_t*>(lo + p + 2) = l1;
    }
}

// ----------------- transpose + split: dst[c][r] = src[r][c] -----------------
__global__ void trans_split(const float* __restrict__ src,
                            __nv_bfloat16* __restrict__ th, __nv_bfloat16* __restrict__ tl,
                            int srows, int scols, long long sBatch, long long dBatch, int soff)
{
    __shared__ float t[32][33];
    const float* s = src + (size_t)blockIdx.z * sBatch + soff;
    int r0 = blockIdx.x * 32, c0 = blockIdx.y * 32;
    int tx = threadIdx.x, ty = threadIdx.y;
    #pragma unroll
    for (int j = 0; j < 32; j += 8)
        t[ty + j][tx] = s[(size_t)(r0 + ty + j) * scols + c0 + tx];
    __syncthreads();
    size_t db = (size_t)blockIdx.z * dBatch;
    #pragma unroll
    for (int j = 0; j < 32; j += 8) {
        float v = t[tx][ty + j];
        __nv_bfloat16 hv = __float2bfloat16(v);
        size_t o = db + (size_t)(c0 + ty + j) * srows + r0 + tx;
        th[o] = hv;
        tl[o] = __float2bfloat16(v - __bfloat162float(hv));
    }
}

// ----------------- launch -----------------
extern "C" void kernel_launch(void* const* d_in, const int* in_sizes, int n_in,
                              void* d_out, int out_size)
{
    const float* x = (const float*)d_in[0];   // [S, D]
    const float* w = (const float*)d_in[1];   // [H, D, 3E]
    float* out = (float*)d_out;               // [S, H*E]

    __nv_bfloat16 *xh, *xl, *wth, *wtl, *qkh, *qkl, *vth, *vtl;
    cudaGetSymbolAddress((void**)&xh, g_xh);
    cudaGetSymbolAddress((void**)&xl, g_xl);
    cudaGetSymbolAddress((void**)&wth, g_wth);
    cudaGetSymbolAddress((void**)&wtl, g_wtl);
    cudaGetSymbolAddress((void**)&qkh, g_qkh);
    cudaGetSymbolAddress((void**)&qkl, g_qkl);
    cudaGetSymbolAddress((void**)&vth, g_vth);
    cudaGetSymbolAddress((void**)&vtl, g_vtl);

    const int smemG = NSTAGE * STAGE_BYTES;   // 98304
    cudaFuncSetAttribute(gemm_bf16x3, cudaFuncAttributeMaxDynamicSharedMemorySize, smemG);
    const int smemF = 6 * FT;                 // 196608
    cudaFuncSetAttribute(flash_attn, cudaFuncAttributeMaxDynamicSharedMemorySize, smemF);

    const float inv_sqrt_e = 0.08838834764831845f;  // 1/sqrt(128)

    // prepass
    split_f32<<<2048, 256>>>(x, xh, xl, (size_t)SEQ * DM);
    trans_split<<<dim3(DM / 32, NE3 / 32, H), dim3(32, 8)>>>(
        w, wth, wtl, DM, NE3, (long long)DM * NE3, (long long)NE3 * DM, 0);

    // 1a) QK: qk[h][s][0:256] = x @ w[h][:, 0:256], Q cols pre-scaled by 1/sqrt(E)
    gemm_bf16x3<<<dim3(SEQ / BM, 256 / BN, H), 256, smemG>>>(
        xh, xl, wth, wtl, qkh, qkl,
        DM, DM, DM, 256,
        0LL, (long long)NE3 * DM, (long long)SEQ * 256, inv_sqrt_e, 128);

    // 1b) V^T: vt[h][e][t] = Wv^T @ x^T  (A = wt rows 256..383, B = x)
    gemm_bf16x3<<<dim3(E / BM, SEQ / BN, H), 256, smemG>>>(
        wth + (size_t)256 * DM, wtl + (size_t)256 * DM, xh, xl, vth, vtl,
        DM, DM, DM, SEQ,
        (long long)NE3 * DM, 0LL, (long long)E * SEQ, 1.0f, 0);

    // 2) fused attention
    flash_attn<<<dim3(SEQ / 128, H), 256, smemF>>>(qkh, qkl, vth, vtl, out);
}

// round 10
// speedup vs baseline: 1.0203x; 1.0203x over previous
#include <cuda_runtime.h>
#include <cuda_bf16.h>
#include <cstdint>
#include <math.h>

#define SEQ 2048
#define DM 2048
#define H 16
#define E 128
#define NE3 384

// ----------------- scratch (static device allocations) -----------------
__device__ __nv_bfloat16 g_xh[(size_t)SEQ * DM];
__device__ __nv_bfloat16 g_xl[(size_t)SEQ * DM];
__device__ __nv_bfloat16 g_wth[(size_t)H * NE3 * DM];    // w transposed: [h][n][k]
__device__ __nv_bfloat16 g_wtl[(size_t)H * NE3 * DM];
__device__ __nv_bfloat16 g_qkh[(size_t)H * SEQ * 256];   // [h][s][Q(0:128)|K(128:256)] hi
__device__ __nv_bfloat16 g_qkl[(size_t)H * SEQ * 256];   // lo
__device__ __nv_bfloat16 g_vth[(size_t)H * E * SEQ];     // V^T: [h][e][t] hi
__device__ __nv_bfloat16 g_vtl[(size_t)H * E * SEQ];     // lo

__device__ __forceinline__ uint32_t smem_u32(const void* p) {
    uint32_t a;
    asm("{ .reg .u64 t; cvta.to.shared.u64 t, %1; cvt.u32.u64 %0, t; }" : "=r"(a) : "l"(p));
    return a;
}
__device__ __forceinline__ float fexp2(float x) {
    float r;
    asm("ex2.approx.f32 %0, %1;" : "=f"(r) : "f"(x));
    return r;
}

#define LDSM4(r, a)                                                              \
    asm volatile("ldmatrix.sync.aligned.m8n8.x4.shared.b16 {%0,%1,%2,%3}, [%4];" \
                 : "=r"((r)[0]), "=r"((r)[1]), "=r"((r)[2]), "=r"((r)[3]) : "r"(a))
#define MMA_BF16(d, a, b0, b1)                                                       \
    asm volatile("mma.sync.aligned.m16n8k16.row.col.f32.bf16.bf16.f32 "              \
                 "{%0,%1,%2,%3},{%4,%5,%6,%7},{%8,%9},{%0,%1,%2,%3};"                \
                 : "+f"((d)[0]), "+f"((d)[1]), "+f"((d)[2]), "+f"((d)[3])            \
                 : "r"((a)[0]), "r"((a)[1]), "r"((a)[2]), "r"((a)[3]), "r"(b0), "r"(b1))

__device__ __forceinline__ uint32_t pack_split(float a, float b, uint32_t& lo) {
    __nv_bfloat16 ha = __float2bfloat16(a), hb = __float2bfloat16(b);
    __nv_bfloat16 la = __float2bfloat16(a - __bfloat162float(ha));
    __nv_bfloat16 lb = __float2bfloat16(b - __bfloat162float(hb));
    lo = (uint32_t)__bfloat16_as_ushort(la) | ((uint32_t)__bfloat16_as_ushort(lb) << 16);
    return (uint32_t)__bfloat16_as_ushort(ha) | ((uint32_t)__bfloat16_as_ushort(hb) << 16);
}

// ================= GEMM tile body: C(bf16 hi/lo) = alpha * A * B^T, bf16x3 ===
// A:[128][2048] K-major rows at pA*, B:[128][2048] K-major rows at pB*.
// Tiles 128x32 bf16 = 8KB, conflict-free additive chunk swizzle (no padding).
constexpr int BK = 32;
constexpr int TILE_BYTES  = 128 * 64;           // 8192 B
constexpr int STAGE_BYTES = 4 * TILE_BYTES;     // Ah, Al, Bh, Bl = 32768 B
constexpr int NSTAGE = 3;                       // 98304 B total -> 2 CTAs/SM
constexpr int GEMM_ITERS = DM / BK;             // 64

__device__ __forceinline__ uint32_t gswz(int row, int c) {
    return (uint32_t)(row * 64 + (((c + (row >> 1)) & 3) << 4));
}

__device__ __forceinline__ void ld_tile(uint32_t dst, const __nv_bfloat16* src, int ld, int tid) {
    #pragma unroll
    for (int j = 0; j < 2; j++) {
        int idx = tid + j * 256;        // 512 chunks: 128 rows x 4 x 16B
        int row = idx >> 2, c = idx & 3;
        uint32_t s = dst + gswz(row, c);
        const __nv_bfloat16* g = src + (size_t)row * ld + c * 8;
        asm volatile("cp.async.cg.shared.global [%0], [%1], 16;" :: "r"(s), "l"(g));
    }
}

template<int LDC>
__device__ __forceinline__ void gemm_tile(
    const __nv_bfloat16* __restrict__ pAh, const __nv_bfloat16* __restrict__ pAl,
    const __nv_bfloat16* __restrict__ pBh, const __nv_bfloat16* __restrict__ pBl,
    __nv_bfloat16* __restrict__ ch, __nv_bfloat16* __restrict__ cl,
    float alpha, uint32_t base, int tid)
{
    const int lane = tid & 31, wid = tid >> 5;
    const int wm = wid & 1;
    const int wn = wid >> 1;

    const int a_row0 = wm * 64 + (lane & 15);
    const int a_csel = lane >> 4;
    const int b_row0 = wn * 32 + ((lane >> 4) << 3) + (lane & 7);
    const int b_csel = (lane >> 3) & 1;

    float acc[4][4][4] = {};

    #pragma unroll
    for (int s = 0; s < NSTAGE - 1; s++) {
        uint32_t sb = base + s * STAGE_BYTES;
        ld_tile(sb,                  pAh + s * BK, DM, tid);
        ld_tile(sb + TILE_BYTES,     pAl + s * BK, DM, tid);
        ld_tile(sb + 2 * TILE_BYTES, pBh + s * BK, DM, tid);
        ld_tile(sb + 3 * TILE_BYTES, pBl + s * BK, DM, tid);
        asm volatile("cp.async.commit_group;" ::: "memory");
    }

    for (int i = 0; i < GEMM_ITERS; i++) {
        asm volatile("cp.async.wait_group %0;" :: "n"(NSTAGE - 2) : "memory");
        __syncthreads();

        const int c = i + NSTAGE - 1;
        if (c < GEMM_ITERS) {
            uint32_t sb = base + (c % NSTAGE) * STAGE_BYTES;
            ld_tile(sb,                  pAh + c * BK, DM, tid);
            ld_tile(sb + TILE_BYTES,     pAl + c * BK, DM, tid);
            ld_tile(sb + 2 * TILE_BYTES, pBh + c * BK, DM, tid);
            ld_tile(sb + 3 * TILE_BYTES, pBl + c * BK, DM, tid);
        }
        asm volatile("cp.async.commit_group;" ::: "memory");   // uniform accounting

        const uint32_t sb   = base + (i % NSTAGE) * STAGE_BYTES;
        const uint32_t sA_h = sb;
        const uint32_t sA_l = sb + TILE_BYTES;
        const uint32_t sB_h = sb + 2 * TILE_BYTES;
        const uint32_t sB_l = sb + 3 * TILE_BYTES;

        #pragma unroll
        for (int kk = 0; kk < 2; kk++) {
            uint32_t fah[4][4], fal[4][4];
            #pragma unroll
            for (int mt = 0; mt < 4; mt++) {
                const uint32_t o = gswz(a_row0 + mt * 16, kk * 2 + a_csel);
                LDSM4(fah[mt], sA_h + o);
                LDSM4(fal[mt], sA_l + o);
            }
            #pragma unroll
            for (int nr = 0; nr < 2; nr++) {
                const uint32_t o = gswz(b_row0 + nr * 16, kk * 2 + b_csel);
                uint32_t fbh[4], fbl[4];
                LDSM4(fbh, sB_h + o);
                LDSM4(fbl, sB_l + o);
                #pragma unroll
                for (int mt = 0; mt < 4; mt++) {
                    MMA_BF16(acc[mt][nr * 2],     fah[mt], fbh[0], fbh[1]);
                    MMA_BF16(acc[mt][nr * 2 + 1], fah[mt], fbh[2], fbh[3]);
                }
                #pragma unroll
                for (int mt = 0; mt < 4; mt++) {
                    MMA_BF16(acc[mt][nr * 2],     fah[mt], fbl[0], fbl[1]);
                    MMA_BF16(acc[mt][nr * 2 + 1], fah[mt], fbl[2], fbl[3]);
                }
                #pragma unroll
                for (int mt = 0; mt < 4; mt++) {
                    MMA_BF16(acc[mt][nr * 2],     fal[mt], fbh[0], fbh[1]);
                    MMA_BF16(acc[mt][nr * 2 + 1], fal[mt], fbh[2], fbh[3]);
                }
            }
        }
    }

    // epilogue: scale and write bf16 hi/lo pairs (tile-local addressing)
    const int er  = wm * 64 + (lane >> 2);
    const int ecb = wn * 32 + (lane & 3) * 2;
    #pragma unroll
    for (int mt = 0; mt < 4; mt++) {
        #pragma unroll
        for (int nt = 0; nt < 4; nt++) {
            const int col = ecb + nt * 8;
            const size_t o0 = (size_t)(er + mt * 16) * LDC + col;
            const size_t o1 = o0 + 8 * (size_t)LDC;
            uint32_t lo, hi;
            hi = pack_split(acc[mt][nt][0] * alpha, acc[mt][nt][1] * alpha, lo);
            *reinterpret_cast<uint32_t*>(ch + o0) = hi;
            *reinterpret_cast<uint32_t*>(cl + o0) = lo;
            hi = pack_split(acc[mt][nt][2] * alpha, acc[mt][nt][3] * alpha, lo);
            *reinterpret_cast<uint32_t*>(ch + o1) = hi;
            *reinterpret_cast<uint32_t*>(cl + o1) = lo;
        }
    }
}

// Fused QKV projection: one launch, 768 CTAs.
//  bid <  512: QK  (1a): m-block x (16), n-block y (2), head z (16)
//  bid >= 512: V^T (1b): n-block y (16), head z (16), m0 = 0
__global__ void __launch_bounds__(256, 2)
gemm_qkv(const __nv_bfloat16* __restrict__ xh, const __nv_bfloat16* __restrict__ xl,
         const __nv_bfloat16* __restrict__ wth, const __nv_bfloat16* __restrict__ wtl,
         __nv_bfloat16* __restrict__ qkh, __nv_bfloat16* __restrict__ qkl,
         __nv_bfloat16* __restrict__ vth, __nv_bfloat16* __restrict__ vtl)
{
    extern __shared__ __align__(1024) char dsm[];
    const uint32_t base = smem_u32(dsm);
    const int tid = threadIdx.x;
    const int bid = blockIdx.x;
    const float inv_sqrt_e = 0.08838834764831845f;  // 1/sqrt(128)

    if (bid < 512) {
        const int x = bid & 15, y = (bid >> 4) & 1, z = bid >> 5;
        const size_t aoff = (size_t)(x * 128) * DM;
        const size_t boff = (size_t)z * NE3 * DM + (size_t)(y * 128) * DM;
        const size_t coff = (size_t)z * SEQ * 256 + (size_t)(x * 128) * 256 + y * 128;
        gemm_tile<256>(xh + aoff, xl + aoff, wth + boff, wtl + boff,
                       qkh + coff, qkl + coff,
                       (y == 0) ? inv_sqrt_e : 1.0f, base, tid);
    } else {
        const int b = bid - 512;
        const int y = b & 15, z = b >> 4;
        const size_t aoff = (size_t)z * NE3 * DM + (size_t)256 * DM;
        const size_t boff = (size_t)(y * 128) * DM;
        const size_t coff = (size_t)z * E * SEQ + y * 128;
        gemm_tile<SEQ>(wth + aoff, wtl + aoff, xh + boff, xl + boff,
                       vth + coff, vtl + coff, 1.0f, base, tid);
    }
}

// ================= fused flash attention =================
constexpr int FT = 32768;                 // bytes per tile
#define FSWZ(row, c) ((uint32_t)((row) * 256 + (((c) ^ ((row) & 7)) << 4)))

__global__ void __launch_bounds__(256, 1)
flash_attn(const __nv_bfloat16* __restrict__ qk_h, const __nv_bfloat16* __restrict__ qk_l,
           const __nv_bfloat16* __restrict__ vt_h, const __nv_bfloat16* __restrict__ vt_l,
           float* __restrict__ out)
{
    extern __shared__ __align__(1024) char fsm[];
    const uint32_t sQh = smem_u32(fsm);
    const uint32_t sQl = sQh + FT, sKh = sQh + 2 * FT, sKl = sQh + 3 * FT;
    const uint32_t sVh = sQh + 4 * FT, sVl = sQh + 5 * FT;

    const int tid = threadIdx.x, lane = tid & 31, wr = tid >> 5;
    const int q0 = blockIdx.x * 128;
    const int h = blockIdx.y;
    const size_t qkB = (size_t)h * SEQ * 256;
    const size_t vB  = (size_t)h * E * SEQ;

    #define FLD(dst, src, ld)                                                             \
        do {                                                                              \
            _Pragma("unroll")                                                             \
            for (int j_ = 0; j_ < 8; j_++) {                                              \
                int idx_ = tid + j_ * 256;                                                \
                int row_ = idx_ >> 4, c_ = idx_ & 15;                                     \
                uint32_t d_ = (dst) + FSWZ(row_, c_);                                     \
                const __nv_bfloat16* g_ = (src) + (size_t)row_ * (ld) + c_ * 8;           \
                asm volatile("cp.async.cg.shared.global [%0], [%1], 16;" :: "r"(d_), "l"(g_)); \
            }                                                                             \
        } while (0)

    // warmup: Q + K0
    FLD(sQh, qk_h + qkB + (size_t)q0 * 256, 256);
    FLD(sQl, qk_l + qkB + (size_t)q0 * 256, 256);
    FLD(sKh, qk_h + qkB + 128, 256);
    FLD(sKl, qk_l + qkB + 128, 256);
    asm volatile("cp.async.commit_group;" ::: "memory");

    float o[16][4] = {};
    float m01 = -1e30f, m23 = -1e30f, l01 = 0.f, l23 = 0.f;
    const float LOG2E = 1.4426950408889634f;

    const int qrow = wr * 16 + (lane & 15);
    const int nrow = ((lane >> 4) << 3) + (lane & 7);

    for (int j = 0; j < 16; j++) {
        asm volatile("cp.async.wait_group 0;" ::: "memory");
        __syncthreads();    // K_j ready; all warps done with V_{j-1}

        // prefetch V_j
        FLD(sVh, vt_h + vB + j * 128, SEQ);
        FLD(sVl, vt_l + vB + j * 128, SEQ);
        asm volatile("cp.async.commit_group;" ::: "memory");

        // ---- S = Q * K_j^T  (bf16x3, np pairs, term-major) ----
        float s[16][4] = {};
        #pragma unroll
        for (int ks = 0; ks < 8; ks++) {
            const int cA = ks * 2 + (lane >> 4);
            const uint32_t aoff = FSWZ(qrow, cA);
            uint32_t qh_f[4], ql_f[4];
            LDSM4(qh_f, sQh + aoff);
            LDSM4(ql_f, sQl + aoff);
            const int cB = ks * 2 + ((lane >> 3) & 1);
            #pragma unroll
            for (int npp = 0; npp < 4; npp++) {
                uint32_t kh2[2][4], kl2[2][4];
                #pragma unroll
                for (int p = 0; p < 2; p++) {
                    const int br = (npp * 2 + p) * 16 + nrow;
                    const uint32_t boff = FSWZ(br, cB);
                    LDSM4(kh2[p], sKh + boff);
                    LDSM4(kl2[p], sKl + boff);
                }
                #pragma unroll
                for (int p = 0; p < 2; p++) {
                    MMA_BF16(s[npp * 4 + 2 * p],     qh_f, kh2[p][0], kh2[p][1]);
                    MMA_BF16(s[npp * 4 + 2 * p + 1], qh_f, kh2[p][2], kh2[p][3]);
                }
                #pragma unroll
                for (int p = 0; p < 2; p++) {
                    MMA_BF16(s[npp * 4 + 2 * p],     qh_f, kl2[p][0], kl2[p][1]);
                    MMA_BF16(s[npp * 4 + 2 * p + 1], qh_f, kl2[p][2], kl2[p][3]);
                }
                #pragma unroll
                for (int p = 0; p < 2; p++) {
                    MMA_BF16(s[npp * 4 + 2 * p],     ql_f, kh2[p][0], kh2[p][1]);
                    MMA_BF16(s[npp * 4 + 2 * p + 1], ql_f, kh2[p][2], kh2[p][3]);
                }
            }
        }

        asm volatile("cp.async.wait_group 0;" ::: "memory");
        __syncthreads();    // V_j ready; all warps done reading K_j

        // prefetch K_{j+1}
        if (j + 1 < 16) {
            FLD(sKh, qk_h + qkB + (size_t)(j + 1) * 128 * 256 + 128, 256);
            FLD(sKl, qk_l + qkB + (size_t)(j + 1) * 128 * 256 + 128, 256);
        }
        asm volatile("cp.async.commit_group;" ::: "memory");

        // ---- online softmax ----
        float nm0 = m01, nm1 = m23;
        #pragma unroll
        for (int nt = 0; nt < 16; nt++) {
            nm0 = fmaxf(nm0, fmaxf(s[nt][0], s[nt][1]));
            nm1 = fmaxf(nm1, fmaxf(s[nt][2], s[nt][3]));
        }
        nm0 = fmaxf(nm0, __shfl_xor_sync(0xffffffffu, nm0, 1));
        nm0 = fmaxf(nm0, __shfl_xor_sync(0xffffffffu, nm0, 2));
        nm1 = fmaxf(nm1, __shfl_xor_sync(0xffffffffu, nm1, 1));
        nm1 = fmaxf(nm1, __shfl_xor_sync(0xffffffffu, nm1, 2));
        const float sc0 = fexp2((m01 - nm0) * LOG2E);
        const float sc1 = fexp2((m23 - nm1) * LOG2E);
        m01 = nm0; m23 = nm1;
        float rs0 = 0.f, rs1 = 0.f;
        #pragma unroll
        for (int nt = 0; nt < 16; nt++) {
            s[nt][0] = fexp2((s[nt][0] - m01) * LOG2E);
            s[nt][1] = fexp2((s[nt][1] - m01) * LOG2E);
            s[nt][2] = fexp2((s[nt][2] - m23) * LOG2E);
            s[nt][3] = fexp2((s[nt][3] - m23) * LOG2E);
            rs0 += s[nt][0] + s[nt][1];
            rs1 += s[nt][2] + s[nt][3];
        }
        rs0 += __shfl_xor_sync(0xffffffffu, rs0, 1);
        rs0 += __shfl_xor_sync(0xffffffffu, rs0, 2);
        rs1 += __shfl_xor_sync(0xffffffffu, rs1, 1);
        rs1 += __shfl_xor_sync(0xffffffffu, rs1, 2);
        l01 = l01 * sc0 + rs0;
        l23 = l23 * sc1 + rs1;
        #pragma unroll
        for (int nt = 0; nt < 16; nt++) {
            o[nt][0] *= sc0; o[nt][1] *= sc0;
            o[nt][2] *= sc1; o[nt][3] *= sc1;
        }

        // ---- O += P * V  (bf16x3, ep pairs, term-major) ----
        #pragma unroll
        for (int ks = 0; ks < 8; ks++) {
            uint32_t ah_f[4], al_f[4];
            ah_f[0] = pack_split(s[2 * ks][0],     s[2 * ks][1],     al_f[0]);
            ah_f[1] = pack_split(s[2 * ks][2],     s[2 * ks][3],     al_f[1]);
            ah_f[2] = pack_split(s[2 * ks + 1][0], s[2 * ks + 1][1], al_f[2]);
            ah_f[3] = pack_split(s[2 * ks + 1][2], s[2 * ks + 1][3], al_f[3]);
            const int cV = ks * 2 + ((lane >> 3) & 1);
            #pragma unroll
            for (int epp = 0; epp < 4; epp++) {
                uint32_t vh2[2][4], vl2[2][4];
                #pragma unroll
                for (int p = 0; p < 2; p++) {
                    const int vr = (epp * 2 + p) * 16 + nrow;
                    const uint32_t voff = FSWZ(vr, cV);
                    LDSM4(vh2[p], sVh + voff);
                    LDSM4(vl2[p], sVl + voff);
                }
                #pragma unroll
                for (int p = 0; p < 2; p++) {
                    MMA_BF16(o[epp * 4 + 2 * p],     ah_f, vh2[p][0], vh2[p][1]);
                    MMA_BF16(o[epp * 4 + 2 * p + 1], ah_f, vh2[p][2], vh2[p][3]);
                }
                #pragma unroll
                for (int p = 0; p < 2; p++) {
                    MMA_BF16(o[epp * 4 + 2 * p],     ah_f, vl2[p][0], vl2[p][1]);
                    MMA_BF16(o[epp * 4 + 2 * p + 1], ah_f, vl2[p][2], vl2[p][3]);
                }
                #pragma unroll
                for (int p = 0; p < 2; p++) {
                    MMA_BF16(o[epp * 4 + 2 * p],     al_f, vh2[p][0], vh2[p][1]);
                    MMA_BF16(o[epp * 4 + 2 * p + 1], al_f, vh2[p][2], vh2[p][3]);
                }
            }
        }
    }

    // epilogue
    const float inv0 = 1.0f / l01, inv1 = 1.0f / l23;
    const int row = q0 + wr * 16 + (lane >> 2);
    float* po = out + (size_t)row * DM + h * 128 + (lane & 3) * 2;
    #pragma unroll
    for (int nt = 0; nt < 16; nt++) {
        float2 v0 = { o[nt][0] * inv0, o[nt][1] * inv0 };
        float2 v1 = { o[nt][2] * inv1, o[nt][3] * inv1 };
        *reinterpret_cast<float2*>(po + nt * 8) = v0;
        *reinterpret_cast<float2*>(po + 8 * DM + nt * 8) = v1;
    }
}

// ----------------- fp32 -> bf16 hi/lo split (x) -----------------
__global__ void split_f32(const float* __restrict__ s,
                          __nv_bfloat16* __restrict__ hi, __nv_bfloat16* __restrict__ lo,
                          size_t nelem)
{
    size_t i = (size_t)blockIdx.x * blockDim.x + threadIdx.x;
    size_t stride = (size_t)gridDim.x * blockDim.x;
    for (size_t p = i * 4; p < nelem; p += stride * 4) {
        float4 v = *reinterpret_cast<const float4*>(s + p);
        uint32_t l0, l1;
        uint32_t h0 = pack_split(v.x, v.y, l0);
        uint32_t h1 = pack_split(v.z, v.w, l1);
        *reinterpret_cast<uint32_t*>(hi + p)     = h0;
        *reinterpret_cast<uint32_t*>(hi + p + 2) = h1;
        *reinterpret_cast<uint32_t*>(lo + p)     = l0;
        *reinterpret_cast<uint32_t*>(lo + p + 2) = l1;
    }
}

// ----------------- transpose + split: dst[c][r] = src[r][c] -----------------
__global__ void trans_split(const float* __restrict__ src,
                            __nv_bfloat16* __restrict__ th, __nv_bfloat16* __restrict__ tl,
                            int srows, int scols, long long sBatch, long long dBatch, int soff)
{
    __shared__ float t[32][33];
    const float* s = src + (size_t)blockIdx.z * sBatch + soff;
    int r0 = blockIdx.x * 32, c0 = blockIdx.y * 32;
    int tx = threadIdx.x, ty = threadIdx.y;
    #pragma unroll
    for (int j = 0; j < 32; j += 8)
        t[ty + j][tx] = s[(size_t)(r0 + ty + j) * scols + c0 + tx];
    __syncthreads();
    size_t db = (size_t)blockIdx.z * dBatch;
    #pragma unroll
    for (int j = 0; j < 32; j += 8) {
        float v = t[tx][ty + j];
        __nv_bfloat16 hv = __float2bfloat16(v);
        size_t o = db + (size_t)(c0 + ty + j) * srows + r0 + tx;
        th[o] = hv;
        tl[o] = __float2bfloat16(v - __bfloat162float(hv));
    }
}

// ----------------- launch -----------------
extern "C" void kernel_launch(void* const* d_in, const int* in_sizes, int n_in,
                              void* d_out, int out_size)
{
    const float* x = (const float*)d_in[0];   // [S, D]
    const float* w = (const float*)d_in[1];   // [H, D, 3E]
    float* out = (float*)d_out;               // [S, H*E]

    __nv_bfloat16 *xh, *xl, *wth, *wtl, *qkh, *qkl, *vth, *vtl;
    cudaGetSymbolAddress((void**)&xh, g_xh);
    cudaGetSymbolAddress((void**)&xl, g_xl);
    cudaGetSymbolAddress((void**)&wth, g_wth);
    cudaGetSymbolAddress((void**)&wtl, g_wtl);
    cudaGetSymbolAddress((void**)&qkh, g_qkh);
    cudaGetSymbolAddress((void**)&qkl, g_qkl);
    cudaGetSymbolAddress((void**)&vth, g_vth);
    cudaGetSymbolAddress((void**)&vtl, g_vtl);

    const int smemG = NSTAGE * STAGE_BYTES;   // 98304
    cudaFuncSetAttribute(gemm_qkv, cudaFuncAttributeMaxDynamicSharedMemorySize, smemG);
    const int smemF = 6 * FT;                 // 196608
    cudaFuncSetAttribute(flash_attn, cudaFuncAttributeMaxDynamicSharedMemorySize, smemF);

    // prepass (exact-cover grid: one float4 per thread)
    split_f32<<<4096, 256>>>(x, xh, xl, (size_t)SEQ * DM);
    trans_split<<<dim3(DM / 32, NE3 / 32, H), dim3(32, 8)>>>(
        w, wth, wtl, DM, NE3, (long long)DM * NE3, (long long)NE3 * DM, 0);

    // 1) fused QK-projection + V^T-projection, one 768-CTA launch
    gemm_qkv<<<768, 256, smemG>>>(xh, xl, wth, wtl, qkh, qkl, vth, vtl);

    // 2) fused attention
    flash_attn<<<dim3(SEQ / 128, H), 256, smemF>>>(qkh, qkl, vth, vtl, out);
}